// round 3
// baseline (speedup 1.0000x reference)
#include <cuda_runtime.h>
#include <math.h>

// Problem constants
#define BB   16
#define CC   256
#define HH   48
#define WW   48
#define NN   2304          // H*W
#define KTOT 2304          // C*9 for 3x3 conv implicit GEMM
#define EPSB 1e-5f

// ---------------------------------------------------------------------------
// Scratch (device globals; allocation-free per harness rules)
// ---------------------------------------------------------------------------
__device__ float g_Q    [(size_t)BB * CC * NN];
__device__ float g_K    [(size_t)BB * CC * NN];
__device__ float g_V    [(size_t)BB * CC * NN];
__device__ float g_fused[(size_t)BB * CC * NN];
__device__ float g_tmp  [(size_t)BB * CC * NN];
__device__ float g_attn [(size_t)BB * NN * NN];

// ---------------------------------------------------------------------------
// Tile config: 128x128 block tile, BK=8, 256 threads, 8x8 per thread
// ---------------------------------------------------------------------------
#define BM 128
#define BN 128
#define BK 8

// ===========================================================================
// Kernel 1: Q/K/V 1x1 conv.  Out[b,o,n] = sum_c W[o,c]*X[b,c,n] + bias[o]
// grid: (NN/128, CC/128, BB)
// ===========================================================================
__global__ __launch_bounds__(256) void k_qkv(
    const float* __restrict__ Wt, const float* __restrict__ bias,
    const float* __restrict__ X, float* __restrict__ Out)
{
    const int bz = blockIdx.z;
    const float* Xb = X   + (size_t)bz * CC * NN;
    float*       Ob = Out + (size_t)bz * CC * NN;
    const int rowT = blockIdx.y * BM;
    const int colT = blockIdx.x * BN;

    __shared__ float As[BK][BM];
    __shared__ float Bs[BK][BN];

    const int tid  = threadIdx.x;
    const int aRow = tid >> 1;           // 0..127
    const int aCol = (tid & 1) << 2;     // 0 or 4
    const int bRow = tid >> 5;           // 0..7
    const int bCol = (tid & 31) << 2;    // 0..124
    const int tr   = (tid >> 4) << 3;
    const int tc   = (tid & 15) << 3;

    float acc[8][8] = {};

    for (int k0 = 0; k0 < CC; k0 += BK) {
        float4 av = *(const float4*)(Wt + (size_t)(rowT + aRow) * CC + k0 + aCol);
        As[aCol + 0][aRow] = av.x; As[aCol + 1][aRow] = av.y;
        As[aCol + 2][aRow] = av.z; As[aCol + 3][aRow] = av.w;
        *(float4*)(&Bs[bRow][bCol]) =
            *(const float4*)(Xb + (size_t)(k0 + bRow) * NN + colT + bCol);
        __syncthreads();
        #pragma unroll
        for (int k = 0; k < BK; k++) {
            float ra[8], rb[8];
            #pragma unroll
            for (int i = 0; i < 8; i++) ra[i] = As[k][tr + i];
            #pragma unroll
            for (int j = 0; j < 8; j++) rb[j] = Bs[k][tc + j];
            #pragma unroll
            for (int i = 0; i < 8; i++)
                #pragma unroll
                for (int j = 0; j < 8; j++)
                    acc[i][j] = fmaf(ra[i], rb[j], acc[i][j]);
        }
        __syncthreads();
    }
    #pragma unroll
    for (int i = 0; i < 8; i++) {
        const float bv = bias[rowT + tr + i];
        float* dst = Ob + (size_t)(rowT + tr + i) * NN + colT + tc;
        #pragma unroll
        for (int j = 0; j < 8; j++) dst[j] = acc[i][j] + bv;
    }
}

// ===========================================================================
// Kernel 2: scores[b,n,m] = sum_c K[b,c,n] * Q[b,c,m]
// grid: (NN/128 (m), NN/128 (n), BB)
// ===========================================================================
__global__ __launch_bounds__(256) void k_scores(
    const float* __restrict__ Kt, const float* __restrict__ Qt,
    float* __restrict__ S)
{
    const int bz = blockIdx.z;
    const float* Kb = Kt + (size_t)bz * CC * NN;
    const float* Qb = Qt + (size_t)bz * CC * NN;
    float*       Sb = S  + (size_t)bz * NN * NN;
    const int rowT = blockIdx.y * BM;   // n
    const int colT = blockIdx.x * BN;   // m

    __shared__ float As[BK][BM];
    __shared__ float Bs[BK][BN];

    const int tid = threadIdx.x;
    const int lK  = tid >> 5;           // 0..7 (k within chunk)
    const int lM  = (tid & 31) << 2;    // 0..124
    const int tr  = (tid >> 4) << 3;
    const int tc  = (tid & 15) << 3;

    float acc[8][8] = {};

    for (int k0 = 0; k0 < CC; k0 += BK) {
        // A tile: K[c, n] contiguous along n -> directly [k][m] layout
        *(float4*)(&As[lK][lM]) =
            *(const float4*)(Kb + (size_t)(k0 + lK) * NN + rowT + lM);
        *(float4*)(&Bs[lK][lM]) =
            *(const float4*)(Qb + (size_t)(k0 + lK) * NN + colT + lM);
        __syncthreads();
        #pragma unroll
        for (int k = 0; k < BK; k++) {
            float ra[8], rb[8];
            #pragma unroll
            for (int i = 0; i < 8; i++) ra[i] = As[k][tr + i];
            #pragma unroll
            for (int j = 0; j < 8; j++) rb[j] = Bs[k][tc + j];
            #pragma unroll
            for (int i = 0; i < 8; i++)
                #pragma unroll
                for (int j = 0; j < 8; j++)
                    acc[i][j] = fmaf(ra[i], rb[j], acc[i][j]);
        }
        __syncthreads();
    }
    #pragma unroll
    for (int i = 0; i < 8; i++) {
        float* dst = Sb + (size_t)(rowT + tr + i) * NN + colT + tc;
        #pragma unroll
        for (int j = 0; j < 8; j++) dst[j] = acc[i][j];
    }
}

// ===========================================================================
// Kernel 3: row softmax over last axis (rows of length NN), in place.
// grid: BB*NN blocks, 256 threads. 9 elems per thread register-resident.
// ===========================================================================
__global__ __launch_bounds__(256) void k_softmax(float* __restrict__ A)
{
    float* p = A + (size_t)blockIdx.x * NN;
    const int tid = threadIdx.x;
    float v[9];
    float mx = -1e30f;
    #pragma unroll
    for (int i = 0; i < 9; i++) {
        v[i] = p[tid + (i << 8)];
        mx = fmaxf(mx, v[i]);
    }
    __shared__ float red[8];
    #pragma unroll
    for (int o = 16; o > 0; o >>= 1)
        mx = fmaxf(mx, __shfl_xor_sync(0xffffffffu, mx, o));
    if ((tid & 31) == 0) red[tid >> 5] = mx;
    __syncthreads();
    float m2 = red[0];
    #pragma unroll
    for (int i = 1; i < 8; i++) m2 = fmaxf(m2, red[i]);
    __syncthreads();

    float s = 0.f;
    #pragma unroll
    for (int i = 0; i < 9; i++) {
        v[i] = __expf(v[i] - m2);
        s += v[i];
    }
    #pragma unroll
    for (int o = 16; o > 0; o >>= 1)
        s += __shfl_xor_sync(0xffffffffu, s, o);
    if ((tid & 31) == 0) red[tid >> 5] = s;
    __syncthreads();
    float s2 = 0.f;
    #pragma unroll
    for (int i = 0; i < 8; i++) s2 += red[i];
    const float inv = 1.0f / s2;
    #pragma unroll
    for (int i = 0; i < 9; i++) p[tid + (i << 8)] = v[i] * inv;
}

// ===========================================================================
// Kernel 4: fused[b,c,m] = F_b[b,c,m] + sum_n V[b,c,n] * attn[b,n,m]
// grid: (NN/128, CC/128, BB).  K-dim = NN.
// ===========================================================================
__global__ __launch_bounds__(256) void k_av(
    const float* __restrict__ Vt, const float* __restrict__ At,
    const float* __restrict__ Fb, float* __restrict__ Out)
{
    const int bz = blockIdx.z;
    const float* Vb = Vt  + (size_t)bz * CC * NN;
    const float* Ab = At  + (size_t)bz * NN * NN;
    const float* Rb = Fb  + (size_t)bz * CC * NN;
    float*       Ob = Out + (size_t)bz * CC * NN;
    const int rowT = blockIdx.y * BM;   // c
    const int colT = blockIdx.x * BN;   // m

    __shared__ float As[BK][BM];
    __shared__ float Bs[BK][BN];

    const int tid  = threadIdx.x;
    const int aRow = tid >> 1;
    const int aCol = (tid & 1) << 2;
    const int bRow = tid >> 5;
    const int bCol = (tid & 31) << 2;
    const int tr   = (tid >> 4) << 3;
    const int tc   = (tid & 15) << 3;

    float acc[8][8] = {};

    for (int k0 = 0; k0 < NN; k0 += BK) {
        float4 av = *(const float4*)(Vb + (size_t)(rowT + aRow) * NN + k0 + aCol);
        As[aCol + 0][aRow] = av.x; As[aCol + 1][aRow] = av.y;
        As[aCol + 2][aRow] = av.z; As[aCol + 3][aRow] = av.w;
        *(float4*)(&Bs[bRow][bCol]) =
            *(const float4*)(Ab + (size_t)(k0 + bRow) * NN + colT + bCol);
        __syncthreads();
        #pragma unroll
        for (int k = 0; k < BK; k++) {
            float ra[8], rb[8];
            #pragma unroll
            for (int i = 0; i < 8; i++) ra[i] = As[k][tr + i];
            #pragma unroll
            for (int j = 0; j < 8; j++) rb[j] = Bs[k][tc + j];
            #pragma unroll
            for (int i = 0; i < 8; i++)
                #pragma unroll
                for (int j = 0; j < 8; j++)
                    acc[i][j] = fmaf(ra[i], rb[j], acc[i][j]);
        }
        __syncthreads();
    }
    #pragma unroll
    for (int i = 0; i < 8; i++) {
        const float* res = Rb + (size_t)(rowT + tr + i) * NN + colT + tc;
        float*       dst = Ob + (size_t)(rowT + tr + i) * NN + colT + tc;
        #pragma unroll
        for (int j = 0; j < 8; j++) dst[j] = acc[i][j] + res[j];
    }
}

// ===========================================================================
// Kernel 5/6: implicit-GEMM 3x3 SAME conv + BN (+relu / +residual epilogue)
// Out[b,o,p] = bn( sum_{c,ky,kx} W[o,c,ky,kx] * In[b,c,y+ky-1,x+kx-1] )
// grid: (NN/128, CC/128, BB). K-dim = C*9 = 2304.
// SECOND=false : out = relu(bn(acc))
// SECOND=true  : f = Res; out = relu(bn(acc) + f) + f
// ===========================================================================
template <bool SECOND>
__global__ __launch_bounds__(256) void k_conv(
    const float* __restrict__ Wt, const float* __restrict__ In,
    const float* __restrict__ bn_s, const float* __restrict__ bn_b,
    const float* __restrict__ bn_m, const float* __restrict__ bn_v,
    const float* __restrict__ Res, float* __restrict__ Out)
{
    const int bz = blockIdx.z;
    const float* Inb = In  + (size_t)bz * CC * NN;
    float*       Ob  = Out + (size_t)bz * CC * NN;
    const int rowT = blockIdx.y * BM;   // o
    const int colT = blockIdx.x * BN;   // p (spatial)

    __shared__ float As[BK][BM];
    __shared__ float Bs[BK][BN];

    const int tid  = threadIdx.x;
    const int aRow = tid >> 1;
    const int aCol = (tid & 1) << 2;
    const int bK   = tid >> 5;          // 0..7
    const int bP   = (tid & 31) << 2;   // 0..124
    const int tr   = (tid >> 4) << 3;
    const int tc   = (tid & 15) << 3;

    // spatial coords for this thread's B-loads (constant over k loop;
    // float4 never crosses an image row since 48 % 4 == 0)
    const int p = colT + bP;
    const int y = p / WW;
    const int x = p - y * WW;

    float acc[8][8] = {};

    for (int k0 = 0; k0 < KTOT; k0 += BK) {
        float4 av = *(const float4*)(Wt + (size_t)(rowT + aRow) * KTOT + k0 + aCol);
        As[aCol + 0][aRow] = av.x; As[aCol + 1][aRow] = av.y;
        As[aCol + 2][aRow] = av.z; As[aCol + 3][aRow] = av.w;

        // im2col on the fly: k = c*9 + ky*3 + kx
        {
            const int kk = k0 + bK;
            const int c  = kk / 9;
            const int r  = kk - c * 9;
            const int ky = r / 3;
            const int kx = r - ky * 3;
            const int sy = y + ky - 1;
            const bool yok = (unsigned)sy < (unsigned)HH;
            const float* src = Inb + (size_t)c * NN + sy * WW;
            #pragma unroll
            for (int u = 0; u < 4; u++) {
                const int sx = x + u + kx - 1;
                Bs[bK][bP + u] =
                    (yok && (unsigned)sx < (unsigned)WW) ? src[sx] : 0.0f;
            }
        }
        __syncthreads();
        #pragma unroll
        for (int k = 0; k < BK; k++) {
            float ra[8], rb[8];
            #pragma unroll
            for (int i = 0; i < 8; i++) ra[i] = As[k][tr + i];
            #pragma unroll
            for (int j = 0; j < 8; j++) rb[j] = Bs[k][tc + j];
            #pragma unroll
            for (int i = 0; i < 8; i++)
                #pragma unroll
                for (int j = 0; j < 8; j++)
                    acc[i][j] = fmaf(ra[i], rb[j], acc[i][j]);
        }
        __syncthreads();
    }

    #pragma unroll
    for (int i = 0; i < 8; i++) {
        const int o = rowT + tr + i;
        const float inv  = bn_s[o] * rsqrtf(bn_v[o] + EPSB);
        const float beta = bn_b[o] - bn_m[o] * inv;
        float*       dst = Ob + (size_t)o * NN + colT + tc;
        const float* res = SECOND ? (Res + (size_t)bz * CC * NN
                                         + (size_t)o * NN + colT + tc)
                                  : nullptr;
        #pragma unroll
        for (int j = 0; j < 8; j++) {
            float val = acc[i][j] * inv + beta;
            if (SECOND) {
                const float f = res[j];
                val = fmaxf(val + f, 0.0f) + f;
            } else {
                val = fmaxf(val, 0.0f);
            }
            dst[j] = val;
        }
    }
}

// ===========================================================================
// Host launcher
// ===========================================================================
extern "C" void kernel_launch(void* const* d_in, const int* in_sizes, int n_in,
                              void* d_out, int out_size)
{
    (void)in_sizes; (void)n_in; (void)out_size;
    const float* F_b  = (const float*)d_in[0];
    const float* F_a  = (const float*)d_in[1];
    const float* qw   = (const float*)d_in[2];
    const float* qb   = (const float*)d_in[3];
    const float* kw   = (const float*)d_in[4];
    const float* kb   = (const float*)d_in[5];
    const float* vw   = (const float*)d_in[6];
    const float* vb   = (const float*)d_in[7];
    const float* c1w  = (const float*)d_in[8];
    const float* bn1s = (const float*)d_in[9];
    const float* bn1b = (const float*)d_in[10];
    const float* bn1m = (const float*)d_in[11];
    const float* bn1v = (const float*)d_in[12];
    const float* c2w  = (const float*)d_in[13];
    const float* bn2s = (const float*)d_in[14];
    const float* bn2b = (const float*)d_in[15];
    const float* bn2m = (const float*)d_in[16];
    const float* bn2v = (const float*)d_in[17];
    float* out = (float*)d_out;

    float *Q, *K, *V, *fused, *tmp, *attn;
    cudaGetSymbolAddress((void**)&Q,     g_Q);
    cudaGetSymbolAddress((void**)&K,     g_K);
    cudaGetSymbolAddress((void**)&V,     g_V);
    cudaGetSymbolAddress((void**)&fused, g_fused);
    cudaGetSymbolAddress((void**)&tmp,   g_tmp);
    cudaGetSymbolAddress((void**)&attn,  g_attn);

    dim3 blk(256);
    dim3 gFeat(NN / BN, CC / BM, BB);   // (18, 2, 16)
    dim3 gScor(NN / BN, NN / BM, BB);   // (18, 18, 16)

    k_qkv<<<gFeat, blk>>>(qw, qb, F_b, Q);
    k_qkv<<<gFeat, blk>>>(kw, kb, F_a, K);
    k_qkv<<<gFeat, blk>>>(vw, vb, F_a, V);
    k_scores<<<gScor, blk>>>(K, Q, attn);
    k_softmax<<<BB * NN, 256>>>(attn);
    k_av<<<gFeat, blk>>>(V, attn, F_b, fused);
    k_conv<false><<<gFeat, blk>>>(c1w, fused, bn1s, bn1b, bn1m, bn1v,
                                  nullptr, tmp);
    k_conv<true><<<gFeat, blk>>>(c2w, tmp, bn2s, bn2b, bn2m, bn2v,
                                 fused, out);
}